// round 3
// baseline (speedup 1.0000x reference)
#include <cuda_runtime.h>
#include <cstdint>

#define H 128
#define H4 32
#define MAXN 50176   // padded capacity (actual N = 50000)

__device__ float g_x[MAXN * H];
__device__ float g_agg[MAXN * H];

// ---------------------------------------------------------------------------
// packed f32x2 helpers (ptxas never auto-fuses FFMA2 from C++; must use PTX)
// ---------------------------------------------------------------------------
__device__ __forceinline__ unsigned long long pack2(float x, float y) {
    unsigned long long r;
    asm("mov.b64 %0, {%1, %2};" : "=l"(r) : "f"(x), "f"(y));
    return r;
}
__device__ __forceinline__ void unpack2(unsigned long long v, float& x, float& y) {
    asm("mov.b64 {%0, %1}, %2;" : "=f"(x), "=f"(y) : "l"(v));
}
__device__ __forceinline__ void fma2(unsigned long long& acc, unsigned long long a,
                                     unsigned long long b) {
    asm("fma.rn.f32x2 %0, %1, %2, %0;" : "+l"(acc) : "l"(a), "l"(b));
}

// ---------------------------------------------------------------------------
// x[n] = emb[z[n]]   (one float4 per thread)
// ---------------------------------------------------------------------------
__global__ void k_embed(const int* __restrict__ z, const float* __restrict__ emb,
                        float* __restrict__ x, int n) {
    int t = blockIdx.x * blockDim.x + threadIdx.x;
    int row = t >> 5;
    int col = t & 31;
    if (row >= n) return;
    int v = z[row];
    reinterpret_cast<float4*>(x)[row * H4 + col] =
        reinterpret_cast<const float4*>(emb)[v * H4 + col];
}

// ---------------------------------------------------------------------------
// edge phase: agg[dst] += relu(x[src] + edge_attr)    (1 warp per edge)
// ---------------------------------------------------------------------------
__global__ void __launch_bounds__(256) k_edge(const int* __restrict__ ei,
                                              const float* __restrict__ ea,
                                              const float* __restrict__ x,
                                              float* __restrict__ agg, int E) {
    int w = (blockIdx.x * blockDim.x + threadIdx.x) >> 5;
    int lane = threadIdx.x & 31;
    if (w >= E) return;
    int s = __ldg(ei + w);
    int d = __ldg(ei + E + w);
    float4 xv = reinterpret_cast<const float4*>(x)[s * H4 + lane];
    float4 ev = reinterpret_cast<const float4*>(ea)[(size_t)w * H4 + lane];
    float m0 = fmaxf(xv.x + ev.x, 0.0f);
    float m1 = fmaxf(xv.y + ev.y, 0.0f);
    float m2 = fmaxf(xv.z + ev.z, 0.0f);
    float m3 = fmaxf(xv.w + ev.w, 0.0f);
    float* p = agg + (size_t)d * H + lane * 4;
    asm volatile("red.global.add.v4.f32 [%0], {%1, %2, %3, %4};"
                 :: "l"(p), "f"(m0), "f"(m1), "f"(m2), "f"(m3)
                 : "memory");
}

// ---------------------------------------------------------------------------
// fused MLP: h1 = relu(agg @ W1 + b1); h2 = h1 @ W2 + b2;
//            out = (relu_out ? relu(h2) : h2) + xin
// agg already contains (scatter-sum + x) because agg was seeded with x.
// Block: 256 threads, 64 rows. smem: W1(64K) W2(64K) In(32K) Hid(32K) = 192KB
// ---------------------------------------------------------------------------
__global__ void __launch_bounds__(256, 1)
k_mlp(const float* __restrict__ agg, const float* __restrict__ xin,
      const float* __restrict__ W1, const float* __restrict__ b1,
      const float* __restrict__ W2, const float* __restrict__ b2,
      float* __restrict__ xout, int n, int relu_out) {
    extern __shared__ float sm[];
    float* sW1 = sm;             // 16384 floats
    float* sW2 = sm + 16384;     // 16384
    float* sIn = sm + 32768;     // 8192  (64 x 128)
    float* sH  = sm + 40960;     // 8192

    const int tid = threadIdx.x;
    const int row0 = blockIdx.x * 64;

    // load weights
    for (int i = tid; i < 4096; i += 256) {
        reinterpret_cast<float4*>(sW1)[i] = reinterpret_cast<const float4*>(W1)[i];
        reinterpret_cast<float4*>(sW2)[i] = reinterpret_cast<const float4*>(W2)[i];
    }
    // load input tile (agg already = scatter_sum + x)
    for (int i = tid; i < 2048; i += 256) {
        int r = i >> 5;
        int row = row0 + r;
        float4 v = make_float4(0.f, 0.f, 0.f, 0.f);
        if (row < n)
            v = reinterpret_cast<const float4*>(agg)[(size_t)row * H4 + (i & 31)];
        reinterpret_cast<float4*>(sIn)[i] = v;
    }
    __syncthreads();

    const int lane = tid & 31;
    const int warp = tid >> 5;
    const int rb = warp << 3;   // 8 rows per warp

    // ---- layer 1 ----
    unsigned long long acc[8][2];
    #pragma unroll
    for (int r = 0; r < 8; ++r) { acc[r][0] = 0ULL; acc[r][1] = 0ULL; }

    const float4* sW1v = reinterpret_cast<const float4*>(sW1);
    for (int k0 = 0; k0 < 128; k0 += 4) {
        float a[8][4];
        #pragma unroll
        for (int r = 0; r < 8; ++r) {
            float4 t = *reinterpret_cast<const float4*>(&sIn[(rb + r) * H + k0]);
            a[r][0] = t.x; a[r][1] = t.y; a[r][2] = t.z; a[r][3] = t.w;
        }
        #pragma unroll
        for (int kk = 0; kk < 4; ++kk) {
            float4 wv = sW1v[(k0 + kk) * H4 + lane];
            unsigned long long w01 = pack2(wv.x, wv.y);
            unsigned long long w23 = pack2(wv.z, wv.w);
            #pragma unroll
            for (int r = 0; r < 8; ++r) {
                unsigned long long aa = pack2(a[r][kk], a[r][kk]);
                fma2(acc[r][0], aa, w01);
                fma2(acc[r][1], aa, w23);
            }
        }
    }
    {
        float4 bv = reinterpret_cast<const float4*>(b1)[lane];
        #pragma unroll
        for (int r = 0; r < 8; ++r) {
            float f0, f1, f2, f3;
            unpack2(acc[r][0], f0, f1);
            unpack2(acc[r][1], f2, f3);
            f0 = fmaxf(f0 + bv.x, 0.f);
            f1 = fmaxf(f1 + bv.y, 0.f);
            f2 = fmaxf(f2 + bv.z, 0.f);
            f3 = fmaxf(f3 + bv.w, 0.f);
            *reinterpret_cast<float4*>(&sH[(rb + r) * H + lane * 4]) =
                make_float4(f0, f1, f2, f3);
        }
    }
    __syncthreads();

    // ---- layer 2 ----
    #pragma unroll
    for (int r = 0; r < 8; ++r) { acc[r][0] = 0ULL; acc[r][1] = 0ULL; }

    const float4* sW2v = reinterpret_cast<const float4*>(sW2);
    for (int k0 = 0; k0 < 128; k0 += 4) {
        float a[8][4];
        #pragma unroll
        for (int r = 0; r < 8; ++r) {
            float4 t = *reinterpret_cast<const float4*>(&sH[(rb + r) * H + k0]);
            a[r][0] = t.x; a[r][1] = t.y; a[r][2] = t.z; a[r][3] = t.w;
        }
        #pragma unroll
        for (int kk = 0; kk < 4; ++kk) {
            float4 wv = sW2v[(k0 + kk) * H4 + lane];
            unsigned long long w01 = pack2(wv.x, wv.y);
            unsigned long long w23 = pack2(wv.z, wv.w);
            #pragma unroll
            for (int r = 0; r < 8; ++r) {
                unsigned long long aa = pack2(a[r][kk], a[r][kk]);
                fma2(acc[r][0], aa, w01);
                fma2(acc[r][1], aa, w23);
            }
        }
    }
    {
        float4 bv = reinterpret_cast<const float4*>(b2)[lane];
        #pragma unroll
        for (int r = 0; r < 8; ++r) {
            int row = row0 + rb + r;
            if (row >= n) continue;
            float f0, f1, f2, f3;
            unpack2(acc[r][0], f0, f1);
            unpack2(acc[r][1], f2, f3);
            f0 += bv.x; f1 += bv.y; f2 += bv.z; f3 += bv.w;
            if (relu_out) {
                f0 = fmaxf(f0, 0.f); f1 = fmaxf(f1, 0.f);
                f2 = fmaxf(f2, 0.f); f3 = fmaxf(f3, 0.f);
            }
            float4 xv = reinterpret_cast<const float4*>(xin)[(size_t)row * H4 + lane];
            reinterpret_cast<float4*>(xout)[(size_t)row * H4 + lane] =
                make_float4(f0 + xv.x, f1 + xv.y, f2 + xv.z, f3 + xv.w);
        }
    }
}

// ---------------------------------------------------------------------------
extern "C" void kernel_launch(void* const* d_in, const int* in_sizes, int n_in,
                              void* d_out, int out_size) {
    const int*   z   = (const int*)d_in[0];
    const int*   ei  = (const int*)d_in[1];
    const float* ea  = (const float*)d_in[2];
    const float* emb = (const float*)d_in[3];
    const float* W1  = (const float*)d_in[4];
    const float* b1  = (const float*)d_in[5];
    const float* W2  = (const float*)d_in[6];
    const float* b2  = (const float*)d_in[7];
    float* out = (float*)d_out;

    const int n = in_sizes[0];
    const int E = in_sizes[1] / 2;

    float *xbuf, *aggbuf;
    cudaGetSymbolAddress((void**)&xbuf, g_x);
    cudaGetSymbolAddress((void**)&aggbuf, g_agg);

    static bool attr_done = false;
    (void)attr_done;  // idempotent; call every time (no state allowed to gate work)
    cudaFuncSetAttribute(k_mlp, cudaFuncAttributeMaxDynamicSharedMemorySize,
                         192 * 1024);

    // embed
    {
        int threads = n * 32;
        k_embed<<<(threads + 255) / 256, 256>>>(z, emb, xbuf, n);
    }

    const size_t nodeBytes = (size_t)n * H * sizeof(float);
    const int edgeBlocks = (E + 7) / 8;   // 8 warps per 256-thread block
    const int mlpBlocks = (n + 63) / 64;

    for (int i = 0; i < 3; ++i) {
        // seed agg with x (folds the "+ x" of GINE aggregation)
        cudaMemcpyAsync(aggbuf, xbuf, nodeBytes, cudaMemcpyDeviceToDevice, 0);
        k_edge<<<edgeBlocks, 256>>>(ei, ea, xbuf, aggbuf, E);
        float* dst = (i == 2) ? out : xbuf;
        k_mlp<<<mlpBlocks, 256, 192 * 1024>>>(aggbuf, xbuf,
                                              W1 + (size_t)i * H * H, b1 + i * H,
                                              W2 + (size_t)i * H * H, b2 + i * H,
                                              dst, n, (i < 2) ? 1 : 0);
    }
}